// round 12
// baseline (speedup 1.0000x reference)
#include <cuda_runtime.h>
#include <cuda_fp16.h>
#include <math.h>
#include <stdint.h>

#define B_      8
#define NSEQ    8192
#define NROWS   65536
#define SCALE_  0.0625f
#define LN_EPS  1e-5f
#define NSEG    8
#define SSEG    1024
#define W2SCALE 64.f
#define W2INV   0.015625f

// ---------------- scratch ----------------------------------------------------
__device__ __half g_qh[(size_t)64 * NSEQ * 32];
__device__ __half g_eh[(size_t)64 * NSEQ * 32];
__device__ __half g_xh[(size_t)NROWS * 256];
__device__ __half g_wh[256 * 768];
__device__ __half g_vh[(size_t)NROWS * 256];
__device__ float g_Apart[64 * NSEG * 1024];
__device__ float g_Sp2[512 * 256];            // [rowblk(128 rows)][k-col]
__device__ float g_A[64 * 1024];
__device__ __half g_w2h[64 * 256 * 256];

// ---------------- PTX helpers ------------------------------------------------
__device__ __forceinline__ uint32_t smem_u32(const void* p) {
    return (uint32_t)__cvta_generic_to_shared(p);
}
__device__ __forceinline__ void cp16(void* dst, const void* src) {
    asm volatile("cp.async.cg.shared.global [%0], [%1], 16;\n"
                 :: "r"(smem_u32(dst)), "l"(src));
}
__device__ __forceinline__ void cp_commit() { asm volatile("cp.async.commit_group;\n"); }
template<int N> __device__ __forceinline__ void cp_wait() {
    asm volatile("cp.async.wait_group %0;\n" :: "n"(N));
}
__device__ __forceinline__ void ldsm4(uint32_t (&r)[4], const void* p) {
    asm volatile("ldmatrix.sync.aligned.m8n8.x4.shared.b16 {%0,%1,%2,%3}, [%4];"
                 : "=r"(r[0]), "=r"(r[1]), "=r"(r[2]), "=r"(r[3]) : "r"(smem_u32(p)));
}
__device__ __forceinline__ void ldsm4t(uint32_t (&r)[4], const void* p) {
    asm volatile("ldmatrix.sync.aligned.m8n8.x4.trans.shared.b16 {%0,%1,%2,%3}, [%4];"
                 : "=r"(r[0]), "=r"(r[1]), "=r"(r[2]), "=r"(r[3]) : "r"(smem_u32(p)));
}
__device__ __forceinline__ void mma16816h(float (&d)[4], const uint32_t (&a)[4], const uint32_t* b) {
    asm volatile("mma.sync.aligned.m16n8k16.row.col.f32.f16.f16.f32 "
                 "{%0,%1,%2,%3}, {%4,%5,%6,%7}, {%8,%9}, {%0,%1,%2,%3};"
                 : "+f"(d[0]), "+f"(d[1]), "+f"(d[2]), "+f"(d[3])
                 : "r"(a[0]), "r"(a[1]), "r"(a[2]), "r"(a[3]), "r"(b[0]), "r"(b[1]));
}

// ============================================================================
// merged convert kernel: x (blocks 0..16383) and Wqkv (blocks 16384..16575)
// ============================================================================
__global__ __launch_bounds__(256) void k_cvt(const float* __restrict__ x,
                                             const float* __restrict__ W) {
    int b = blockIdx.x;
    if (b < 16384) {
        size_t i = ((size_t)b * 256 + threadIdx.x) * 4;
        float4 v = *(const float4*)(x + i);
        *(__half2*)(g_xh + i)     = __halves2half2(__float2half(v.x), __float2half(v.y));
        *(__half2*)(g_xh + i + 2) = __halves2half2(__float2half(v.z), __float2half(v.w));
    } else {
        size_t i = ((size_t)(b - 16384) * 256 + threadIdx.x) * 4;
        float4 v = *(const float4*)(W + i);
        *(__half2*)(g_wh + i)     = __halves2half2(__float2half(v.x), __float2half(v.y));
        *(__half2*)(g_wh + i + 2) = __halves2half2(__float2half(v.z), __float2half(v.w));
    }
}

// ============================================================================
// K1: qkv = x @ Wqkv, fp16 mma, f32 accum.  BM=128, BN=128, BK=32, 256 thr,
// 4 stages, 2 CTAs/SM.  grid (6 colblk fastest, 512 rowblk).
// ============================================================================
#define K1_STG 9472
__global__ __launch_bounds__(256, 2) void k1_gemm() {
    extern __shared__ __half sm[];
    const int tid = threadIdx.x, lane = tid & 31, warp = tid >> 5;
    const int mw = warp >> 2, nw = warp & 3;
    const int row0 = blockIdx.y * 128, col0 = blockIdx.x * 128;

    __half *sA[4], *sB[4];
    #pragma unroll
    for (int s = 0; s < 4; s++) {
        sA[s] = sm + s * K1_STG;
        sB[s] = sm + s * K1_STG + 5120;
    }

    auto load_stage = [&](int s, int kt) {
        const int k0 = kt * 32;
        #pragma unroll
        for (int i = 0; i < 2; i++) {
            int id = tid * 2 + i; int ar = id >> 2; int ac = (id & 3) * 8;
            cp16(sA[s] + ar * 40 + ac, g_xh + (size_t)(row0 + ar) * 256 + k0 + ac);
        }
        #pragma unroll
        for (int i = 0; i < 2; i++) {
            int id = tid * 2 + i; int br = id >> 4; int bc = (id & 15) * 8;
            cp16(sB[s] + br * 136 + bc, g_wh + (size_t)(k0 + br) * 768 + col0 + bc);
        }
        cp_commit();
    };

    float acc[4][4][4];
    #pragma unroll
    for (int mt = 0; mt < 4; mt++)
        #pragma unroll
        for (int nt = 0; nt < 4; nt++)
            #pragma unroll
            for (int i = 0; i < 4; i++) acc[mt][nt][i] = 0.f;

    load_stage(0, 0);
    load_stage(1, 1);
    load_stage(2, 2);
    for (int kt = 0; kt < 8; kt++) {
        int cur = kt & 3;
        if (kt < 5)       { load_stage((kt + 3) & 3, kt + 3); cp_wait<3>(); }
        else if (kt == 5) cp_wait<2>();
        else if (kt == 6) cp_wait<1>();
        else              cp_wait<0>();
        __syncthreads();
        #pragma unroll
        for (int sub = 0; sub < 2; sub++) {
            uint32_t af[4][4], bf[2][4];
            #pragma unroll
            for (int mt = 0; mt < 4; mt++) {
                int r = mw * 64 + mt * 16 + (lane & 15);
                int c = sub * 16 + ((lane >> 4) << 3);
                ldsm4(af[mt], sA[cur] + r * 40 + c);
            }
            #pragma unroll
            for (int bt = 0; bt < 2; bt++) {
                int r = sub * 16 + (lane & 15);
                int c = nw * 32 + bt * 16 + ((lane >> 4) << 3);
                ldsm4t(bf[bt], sB[cur] + r * 136 + c);
            }
            #pragma unroll
            for (int mt = 0; mt < 4; mt++)
                #pragma unroll
                for (int nt = 0; nt < 4; nt++)
                    mma16816h(acc[mt][nt], af[mt], &bf[nt >> 1][(nt & 1) * 2]);
        }
        __syncthreads();
    }

    float scol[4][2];
    #pragma unroll
    for (int nt = 0; nt < 4; nt++) { scol[nt][0] = 0.f; scol[nt][1] = 0.f; }

    #pragma unroll
    for (int mt = 0; mt < 4; mt++) {
        int r = row0 + mw * 64 + mt * 16 + (lane >> 2);
        int b = r >> 13, n = r & 8191;
        #pragma unroll
        for (int nt = 0; nt < 4; nt++) {
            int c = col0 + nw * 32 + nt * 8 + ((lane & 3) << 1);
            float2 p0 = make_float2(acc[mt][nt][0], acc[mt][nt][1]);
            float2 p1 = make_float2(acc[mt][nt][2], acc[mt][nt][3]);
            if (c < 256) {                      // q
                int h = c >> 5, e = c & 31;
                size_t o0 = ((size_t)(b * 8 + h) * NSEQ + n) * 32 + e;
                *(__half2*)(g_qh + o0)       = __halves2half2(__float2half(p0.x), __float2half(p0.y));
                *(__half2*)(g_qh + o0 + 256) = __halves2half2(__float2half(p1.x), __float2half(p1.y));
            } else if (c < 512) {               // exp(k)
                int ck = c - 256;
                int h = ck >> 5, e = ck & 31;
                float e00 = __expf(p0.x), e01 = __expf(p0.y);
                float e10 = __expf(p1.x), e11 = __expf(p1.y);
                scol[nt][0] += e00 + e10;
                scol[nt][1] += e01 + e11;
                size_t o0 = ((size_t)(b * 8 + h) * NSEQ + n) * 32 + e;
                *(__half2*)(g_eh + o0)       = __halves2half2(__float2half(e00), __float2half(e01));
                *(__half2*)(g_eh + o0 + 256) = __halves2half2(__float2half(e10), __float2half(e11));
            } else {                            // v
                int cv = c - 512;
                *(__half2*)(g_vh + (size_t)r * 256 + cv) =
                    __halves2half2(__float2half(p0.x), __float2half(p0.y));
                *(__half2*)(g_vh + (size_t)(r + 8) * 256 + cv) =
                    __halves2half2(__float2half(p1.x), __float2half(p1.y));
            }
        }
    }

    if (col0 == 256 || col0 == 384) {
        __syncthreads();
        float* sS = (float*)sm;  // [128 cols][16 groups]
        int grp = mw * 8 + (lane >> 2);
        #pragma unroll
        for (int nt = 0; nt < 4; nt++)
            #pragma unroll
            for (int p = 0; p < 2; p++) {
                int ckL = nw * 32 + nt * 8 + ((lane & 3) << 1) + p;
                sS[ckL * 16 + grp] = scol[nt][p];
            }
        __syncthreads();
        if (tid < 128) {
            float s = 0.f;
            #pragma unroll
            for (int g = 0; g < 16; g++) s += sS[tid * 16 + g];
            g_Sp2[(size_t)blockIdx.y * 256 + (col0 - 256) + tid] = s;
        }
    }
}

// ============================================================================
// K2: tensor-core stats, fp16 inputs / f32 accum (unchanged).
// ============================================================================
__global__ __launch_bounds__(256) void k_stats() {
    extern __shared__ __half sms[];
    int bh = blockIdx.x, seg = blockIdx.y;
    int tid = threadIdx.x, warp = tid >> 5, lane = tid & 31;

    __half* wbase = sms + warp * 2560;
    const size_t rowbase = ((size_t)bh * NSEQ + seg * SSEG + warp * 128) * 32;
    const __half* Q = g_qh + rowbase;
    const __half* E = g_eh + rowbase;

    const int lr = lane & 15;
    const int lc = (lane >> 4) * 16;

    auto prefetch = [&](int st, int s) {
        __half* sb = wbase + st * 1280;
        size_t src = (size_t)(s * 16 + lr) * 32 + lc;
        cp16(sb +   0 + lr * 40 + lc, Q + src);
        cp16(sb +   8 + lr * 40 + lc, Q + src + 8);
        cp16(sb + 640 + lr * 40 + lc, E + src);
        cp16(sb + 648 + lr * 40 + lc, E + src + 8);
        cp_commit();
    };

    float acc[2][4][4];
    #pragma unroll
    for (int dt = 0; dt < 2; dt++)
        #pragma unroll
        for (int nt = 0; nt < 4; nt++)
            #pragma unroll
            for (int i = 0; i < 4; i++) acc[dt][nt][i] = 0.f;

    const int ar = (lane & 7) | ((lane & 16) >> 1);
    const int ac = lane & 8;
    const int br = lane & 15;
    const int bc = (lane >> 4) << 3;

    prefetch(0, 0);
    for (int s = 0; s < 8; s++) {
        if (s < 7) { prefetch((s + 1) & 1, s + 1); cp_wait<1>(); }
        else cp_wait<0>();
        __syncwarp();
        __half* sb = wbase + (s & 1) * 1280;
        uint32_t Af[2][4], Bf[2][4];
        #pragma unroll
        for (int dt = 0; dt < 2; dt++)
            ldsm4t(Af[dt], sb + 640 + ar * 40 + dt * 16 + ac);
        #pragma unroll
        for (int et = 0; et < 2; et++)
            ldsm4t(Bf[et], sb + br * 40 + et * 16 + bc);
        #pragma unroll
        for (int dt = 0; dt < 2; dt++)
            #pragma unroll
            for (int nt = 0; nt < 4; nt++)
                mma16816h(acc[dt][nt], Af[dt], &Bf[nt >> 1][(nt & 1) * 2]);
        __syncwarp();
    }

    float* red = (float*)(sms + 8 * 2560);
    int gr = lane >> 2, tc = lane & 3;
    #pragma unroll
    for (int dt = 0; dt < 2; dt++)
        #pragma unroll
        for (int nt = 0; nt < 4; nt++) {
            int d0 = dt * 16 + gr, e0 = nt * 8 + tc * 2;
            red[warp * 1024 + d0 * 32 + e0]           = acc[dt][nt][0];
            red[warp * 1024 + d0 * 32 + e0 + 1]       = acc[dt][nt][1];
            red[warp * 1024 + (d0 + 8) * 32 + e0]     = acc[dt][nt][2];
            red[warp * 1024 + (d0 + 8) * 32 + e0 + 1] = acc[dt][nt][3];
        }
    __syncthreads();
    float* ap = g_Apart + ((size_t)bh * NSEG + seg) * 1024;
    #pragma unroll
    for (int c = 0; c < 4; c++) {
        int idx = tid * 4 + c;
        float s = 0.f;
        #pragma unroll
        for (int w = 0; w < 8; w++) s += red[w * 1024 + idx];
        ap[idx] = s;
    }
}

// ============================================================================
// K3a: combine -> g_A (64 blocks). sinv reduction fully parallel.
// ============================================================================
__global__ __launch_bounds__(256) void k_combine() {
    int bh = blockIdx.x, tid = threadIdx.x;
    int b = bh >> 3, h = bh & 7;
    __shared__ float partS[8][32];
    __shared__ float sinv[32];
    {
        int j = tid & 31, part = tid >> 5;     // 8 parts x 32 cols
        float s = 0.f;
        for (int rb = part; rb < 64; rb += 8)
            s += g_Sp2[(size_t)(b * 64 + rb) * 256 + h * 32 + j];
        partS[part][j] = s;
    }
    __syncthreads();
    if (tid < 32) {
        float t = 0.f;
        #pragma unroll
        for (int w = 0; w < 8; w++) t += partS[w][tid];
        sinv[tid] = SCALE_ / t;
    }
    __syncthreads();
    for (int idx = tid; idx < 1024; idx += 256) {
        float a = 0.f;
        for (int seg = 0; seg < NSEG; seg++)
            a += g_Apart[((size_t)bh * NSEG + seg) * 1024 + idx];
        g_A[bh * 1024 + idx] = a * sinv[idx >> 5];
    }
}

// ============================================================================
// K3b: W2[bh][l*32+d][c] = W2SCALE * sum_e A[d][e]*Wout[l*32+e][c]  grid(64,8)
// ============================================================================
__global__ __launch_bounds__(256) void k_w2(const float* __restrict__ Wout) {
    __shared__ float A_s[1024];
    __shared__ float Wsh[32 * 256];
    int bh = blockIdx.x, l = blockIdx.y, tid = threadIdx.x;
    for (int i = tid; i < 1024; i += 256) A_s[i] = g_A[bh * 1024 + i];
    {
        const float4* wsrc = (const float4*)(Wout + l * 32 * 256);
        float4* wdst = (float4*)Wsh;
        for (int i = tid; i < 2048; i += 256) wdst[i] = wsrc[i];
    }
    __syncthreads();
    int c = tid;
    for (int d = 0; d < 32; d++) {
        float s = 0.f;
        #pragma unroll
        for (int e = 0; e < 32; e++) s += A_s[d * 32 + e] * Wsh[e * 256 + c];
        g_w2h[(size_t)bh * 65536 + (size_t)(l * 32 + d) * 256 + c] = __float2half(s * W2SCALE);
    }
}

// ============================================================================
// K4: per (b,h): Y = Vcat @ W2 * (1/W2SCALE) + bias, LayerNorm, write out.
// BM=128, BN=256, BK=32, 512 thr, 4 stages.
// ============================================================================
#define K4_STG 13568
__global__ __launch_bounds__(512, 1) void k4_out(const float* __restrict__ bout,
                                                 const float* __restrict__ gamma,
                                                 const float* __restrict__ beta,
                                                 float* __restrict__ out) {
    extern __shared__ __half sm[];
    const int tid = threadIdx.x, lane = tid & 31, warp = tid >> 5;
    const int mw = warp >> 3, nw = warp & 7;
    const int bh = blockIdx.y, b = bh >> 3, h = bh & 7;
    const int t0 = blockIdx.x * 128;

    __half *sA[4], *sB[4];
    #pragma unroll
    for (int s = 0; s < 4; s++) {
        sA[s] = sm + s * K4_STG;
        sB[s] = sm + s * K4_STG + 5120;
    }

    auto load_stage = [&](int s, int kt) {
        {
            int ar = tid >> 2; int ac = (tid & 3) * 8;
            const size_t go = ((size_t)(b * 8192) + (size_t)(t0 + ar) * 8 + kt) * 256 + h * 32 + ac;
            cp16(sA[s] + ar * 40 + ac, g_vh + go);
        }
        #pragma unroll
        for (int i = 0; i < 2; i++) {
            int id = tid * 2 + i; int br = id >> 5; int bc = (id & 31) * 8;
            const size_t go = (size_t)bh * 65536 + (size_t)(kt * 32 + br) * 256 + bc;
            cp16(sB[s] + br * 264 + bc, g_w2h + go);
        }
        cp_commit();
    };

    float acc[4][4][4];
    #pragma unroll
    for (int mt = 0; mt < 4; mt++)
        #pragma unroll
        for (int nt = 0; nt < 4; nt++)
            #pragma unroll
            for (int i = 0; i < 4; i++) acc[mt][nt][i] = 0.f;

    load_stage(0, 0);
    load_stage(1, 1);
    load_stage(2, 2);
    for (int kt = 0; kt < 8; kt++) {
        int cur = kt & 3;
        if (kt < 5)       { load_stage((kt + 3) & 3, kt + 3); cp_wait<3>(); }
        else if (kt == 5) cp_wait<2>();
        else if (kt == 6) cp_wait<1>();
        else              cp_wait<0>();
        __syncthreads();
        #pragma unroll
        for (int sub = 0; sub < 2; sub++) {
            uint32_t af[4][4], bf[2][4];
            #pragma unroll
            for (int mt = 0; mt < 4; mt++) {
                int r = mw * 64 + mt * 16 + (lane & 15);
                int c = sub * 16 + ((lane >> 4) << 3);
                ldsm4(af[mt], sA[cur] + r * 40 + c);
            }
            #pragma unroll
            for (int bt = 0; bt < 2; bt++) {
                int r = sub * 16 + (lane & 15);
                int c = nw * 32 + bt * 16 + ((lane >> 4) << 3);
                ldsm4t(bf[bt], sB[cur] + r * 264 + c);
            }
            #pragma unroll
            for (int mt = 0; mt < 4; mt++)
                #pragma unroll
                for (int nt = 0; nt < 4; nt++)
                    mma16816h(acc[mt][nt], af[mt], &bf[nt >> 1][(nt & 1) * 2]);
        }
        __syncthreads();
    }

    // ---------------- epilogue: unscale + bias + LayerNorm --------------------
    float* red   = (float*)sm;
    float* sred  = red;            // [128][8]
    float* s2red = red + 1024;     // [128][8]
    float* mus   = red + 2048;     // [128]
    float* rst   = red + 2176;     // [128]

    float bo[4][2];
    #pragma unroll
    for (int nt = 0; nt < 4; nt++) {
        int c = nw * 32 + nt * 8 + ((lane & 3) << 1);
        float2 bv = *(const float2*)(bout + c);
        bo[nt][0] = bv.x; bo[nt][1] = bv.y;
    }

    #pragma unroll
    for (int mt = 0; mt < 4; mt++)
        #pragma unroll
        for (int half = 0; half < 2; half++) {
            float s = 0.f, s2 = 0.f;
            #pragma unroll
            for (int nt = 0; nt < 4; nt++) {
                float v0 = acc[mt][nt][half * 2 + 0] * W2INV + bo[nt][0];
                float v1 = acc[mt][nt][half * 2 + 1] * W2INV + bo[nt][1];
                s += v0 + v1; s2 += v0 * v0 + v1 * v1;
            }
            s  += __shfl_xor_sync(0xffffffffu, s, 1);
            s  += __shfl_xor_sync(0xffffffffu, s, 2);
            s2 += __shfl_xor_sync(0xffffffffu, s2, 1);
            s2 += __shfl_xor_sync(0xffffffffu, s2, 2);
            if ((lane & 3) == 0) {
                int rl = mw * 64 + mt * 16 + (lane >> 2) + half * 8;
                sred[rl * 8 + nw] = s;
                s2red[rl * 8 + nw] = s2;
            }
        }
    __syncthreads();
    if (tid < 128) {
        float s = 0.f, s2 = 0.f;
        #pragma unroll
        for (int w = 0; w < 8; w++) { s += sred[tid * 8 + w]; s2 += s2red[tid * 8 + w]; }
        float mu = s * (1.f / 256.f);
        float var = s2 * (1.f / 256.f) - mu * mu;
        mus[tid] = mu;
        rst[tid] = rsqrtf(var + LN_EPS);
    }
    __syncthreads();

    #pragma unroll
    for (int mt = 0; mt < 4; mt++)
        #pragma unroll
        for (int half = 0; half < 2; half++) {
            int rl = mw * 64 + mt * 16 + (lane >> 2) + half * 8;
            float mu = mus[rl], rs = rst[rl];
            size_t orow = ((size_t)b * 8192 + (size_t)h * 1024 + t0 + rl) * 256;
            #pragma unroll
            for (int nt = 0; nt < 4; nt++) {
                int c = nw * 32 + nt * 8 + ((lane & 3) << 1);
                float2 g = *(const float2*)(gamma + c);
                float2 be = *(const float2*)(beta + c);
                float v0 = acc[mt][nt][half * 2 + 0] * W2INV + bo[nt][0];
                float v1 = acc[mt][nt][half * 2 + 1] * W2INV + bo[nt][1];
                float2 o = make_float2((v0 - mu) * rs * g.x + be.x,
                                       (v1 - mu) * rs * g.y + be.y);
                *(float2*)(out + orow + c) = o;
            }
        }
}

// ============================================================================
extern "C" void kernel_launch(void* const* d_in, const int* in_sizes, int n_in,
                              void* d_out, int out_size) {
    const float* x     = (const float*)d_in[0];
    const float* Wqkv  = (const float*)d_in[1];
    const float* Wout  = (const float*)d_in[2];
    const float* bout  = (const float*)d_in[3];
    const float* gamma = (const float*)d_in[4];
    const float* beta  = (const float*)d_in[5];
    float* out = (float*)d_out;

    const int statsSmem = 8 * 2560 * 2 + 8 * 1024 * 4;
    cudaFuncSetAttribute(k1_gemm, cudaFuncAttributeMaxDynamicSharedMemorySize, 4 * K1_STG * 2);
    cudaFuncSetAttribute(k_stats, cudaFuncAttributeMaxDynamicSharedMemorySize, statsSmem);
    cudaFuncSetAttribute(k4_out,  cudaFuncAttributeMaxDynamicSharedMemorySize, 4 * K4_STG * 2);

    k_cvt<<<16576, 256>>>(x, Wqkv);
    k1_gemm<<<dim3(6, 512), 256, 4 * K1_STG * 2>>>();
    k_stats<<<dim3(64, NSEG), 256, statsSmem>>>();
    k_combine<<<64, 256>>>();
    k_w2<<<dim3(64, 8), 256>>>(Wout);
    k4_out<<<dim3(8, 64), 512, 4 * K4_STG * 2>>>(bout, gamma, beta, out);
}

// round 13
// speedup vs baseline: 1.0539x; 1.0539x over previous
#include <cuda_runtime.h>
#include <cuda_fp16.h>
#include <math.h>
#include <stdint.h>

#define B_      8
#define NSEQ    8192
#define NROWS   65536
#define SCALE_  0.0625f
#define LN_EPS  1e-5f
#define NSEG    8
#define SSEG    1024
#define W2SCALE 64.f
#define W2INV   0.015625f

// ---------------- scratch ----------------------------------------------------
__device__ __half g_qh[(size_t)64 * NSEQ * 32];
__device__ __half g_eh[(size_t)64 * NSEQ * 32];
__device__ __half g_xh[(size_t)NROWS * 256];
__device__ __half g_wh[256 * 768];
__device__ __half g_vh[(size_t)NROWS * 256];
__device__ float g_Apart[64 * NSEG * 1024];
__device__ float g_Sp2[512 * 256];            // [rowblk(128 rows)][k-col]
__device__ float g_A[64 * 1024];
__device__ __half g_w2h[64 * 256 * 256];

// ---------------- PTX helpers ------------------------------------------------
__device__ __forceinline__ uint32_t smem_u32(const void* p) {
    return (uint32_t)__cvta_generic_to_shared(p);
}
__device__ __forceinline__ void cp16(void* dst, const void* src) {
    asm volatile("cp.async.cg.shared.global [%0], [%1], 16;\n"
                 :: "r"(smem_u32(dst)), "l"(src));
}
__device__ __forceinline__ void cp_commit() { asm volatile("cp.async.commit_group;\n"); }
template<int N> __device__ __forceinline__ void cp_wait() {
    asm volatile("cp.async.wait_group %0;\n" :: "n"(N));
}
__device__ __forceinline__ void ldsm4(uint32_t (&r)[4], const void* p) {
    asm volatile("ldmatrix.sync.aligned.m8n8.x4.shared.b16 {%0,%1,%2,%3}, [%4];"
                 : "=r"(r[0]), "=r"(r[1]), "=r"(r[2]), "=r"(r[3]) : "r"(smem_u32(p)));
}
__device__ __forceinline__ void ldsm4t(uint32_t (&r)[4], const void* p) {
    asm volatile("ldmatrix.sync.aligned.m8n8.x4.trans.shared.b16 {%0,%1,%2,%3}, [%4];"
                 : "=r"(r[0]), "=r"(r[1]), "=r"(r[2]), "=r"(r[3]) : "r"(smem_u32(p)));
}
__device__ __forceinline__ void mma16816h(float (&d)[4], const uint32_t (&a)[4], const uint32_t* b) {
    asm volatile("mma.sync.aligned.m16n8k16.row.col.f32.f16.f16.f32 "
                 "{%0,%1,%2,%3}, {%4,%5,%6,%7}, {%8,%9}, {%0,%1,%2,%3};"
                 : "+f"(d[0]), "+f"(d[1]), "+f"(d[2]), "+f"(d[3])
                 : "r"(a[0]), "r"(a[1]), "r"(a[2]), "r"(a[3]), "r"(b[0]), "r"(b[1]));
}

// ============================================================================
// merged convert kernel: x (blocks 0..16383) and Wqkv (blocks 16384..16575)
// ============================================================================
__global__ __launch_bounds__(256) void k_cvt(const float* __restrict__ x,
                                             const float* __restrict__ W) {
    int b = blockIdx.x;
    if (b < 16384) {
        size_t i = ((size_t)b * 256 + threadIdx.x) * 4;
        float4 v = *(const float4*)(x + i);
        *(__half2*)(g_xh + i)     = __halves2half2(__float2half(v.x), __float2half(v.y));
        *(__half2*)(g_xh + i + 2) = __halves2half2(__float2half(v.z), __float2half(v.w));
    } else {
        size_t i = ((size_t)(b - 16384) * 256 + threadIdx.x) * 4;
        float4 v = *(const float4*)(W + i);
        *(__half2*)(g_wh + i)     = __halves2half2(__float2half(v.x), __float2half(v.y));
        *(__half2*)(g_wh + i + 2) = __halves2half2(__float2half(v.z), __float2half(v.w));
    }
}

// ============================================================================
// K1: qkv = x @ Wqkv, fp16 mma, f32 accum.  BM=128, BN=128, BK=32, 256 thr,
// 4 stages, 2 CTAs/SM, single-sync mainloop. grid (6 colblk, 512 rowblk).
// ============================================================================
#define K1_STG 9472
__global__ __launch_bounds__(256, 2) void k1_gemm() {
    extern __shared__ __half sm[];
    const int tid = threadIdx.x, lane = tid & 31, warp = tid >> 5;
    const int mw = warp >> 2, nw = warp & 3;
    const int row0 = blockIdx.y * 128, col0 = blockIdx.x * 128;

    __half *sA[4], *sB[4];
    #pragma unroll
    for (int s = 0; s < 4; s++) {
        sA[s] = sm + s * K1_STG;
        sB[s] = sm + s * K1_STG + 5120;
    }

    auto load_stage = [&](int s, int kt) {
        const int k0 = kt * 32;
        #pragma unroll
        for (int i = 0; i < 2; i++) {
            int id = tid * 2 + i; int ar = id >> 2; int ac = (id & 3) * 8;
            cp16(sA[s] + ar * 40 + ac, g_xh + (size_t)(row0 + ar) * 256 + k0 + ac);
        }
        #pragma unroll
        for (int i = 0; i < 2; i++) {
            int id = tid * 2 + i; int br = id >> 4; int bc = (id & 15) * 8;
            cp16(sB[s] + br * 136 + bc, g_wh + (size_t)(k0 + br) * 768 + col0 + bc);
        }
        cp_commit();
    };

    float acc[4][4][4];
    #pragma unroll
    for (int mt = 0; mt < 4; mt++)
        #pragma unroll
        for (int nt = 0; nt < 4; nt++)
            #pragma unroll
            for (int i = 0; i < 4; i++) acc[mt][nt][i] = 0.f;

    load_stage(0, 0);
    load_stage(1, 1);
    load_stage(2, 2);
    for (int kt = 0; kt < 8; kt++) {
        int cur = kt & 3;
        if (kt < 6)       cp_wait<2>();
        else if (kt == 6) cp_wait<1>();
        else              cp_wait<0>();
        __syncthreads();
        if (kt < 5) load_stage((kt + 3) & 3, kt + 3);
        #pragma unroll
        for (int sub = 0; sub < 2; sub++) {
            uint32_t af[4][4], bf[2][4];
            #pragma unroll
            for (int mt = 0; mt < 4; mt++) {
                int r = mw * 64 + mt * 16 + (lane & 15);
                int c = sub * 16 + ((lane >> 4) << 3);
                ldsm4(af[mt], sA[cur] + r * 40 + c);
            }
            #pragma unroll
            for (int bt = 0; bt < 2; bt++) {
                int r = sub * 16 + (lane & 15);
                int c = nw * 32 + bt * 16 + ((lane >> 4) << 3);
                ldsm4t(bf[bt], sB[cur] + r * 136 + c);
            }
            #pragma unroll
            for (int mt = 0; mt < 4; mt++)
                #pragma unroll
                for (int nt = 0; nt < 4; nt++)
                    mma16816h(acc[mt][nt], af[mt], &bf[nt >> 1][(nt & 1) * 2]);
        }
    }

    float scol[4][2];
    #pragma unroll
    for (int nt = 0; nt < 4; nt++) { scol[nt][0] = 0.f; scol[nt][1] = 0.f; }

    #pragma unroll
    for (int mt = 0; mt < 4; mt++) {
        int r = row0 + mw * 64 + mt * 16 + (lane >> 2);
        int b = r >> 13, n = r & 8191;
        #pragma unroll
        for (int nt = 0; nt < 4; nt++) {
            int c = col0 + nw * 32 + nt * 8 + ((lane & 3) << 1);
            float2 p0 = make_float2(acc[mt][nt][0], acc[mt][nt][1]);
            float2 p1 = make_float2(acc[mt][nt][2], acc[mt][nt][3]);
            if (c < 256) {                      // q
                int h = c >> 5, e = c & 31;
                size_t o0 = ((size_t)(b * 8 + h) * NSEQ + n) * 32 + e;
                *(__half2*)(g_qh + o0)       = __halves2half2(__float2half(p0.x), __float2half(p0.y));
                *(__half2*)(g_qh + o0 + 256) = __halves2half2(__float2half(p1.x), __float2half(p1.y));
            } else if (c < 512) {               // exp(k)
                int ck = c - 256;
                int h = ck >> 5, e = ck & 31;
                float e00 = __expf(p0.x), e01 = __expf(p0.y);
                float e10 = __expf(p1.x), e11 = __expf(p1.y);
                scol[nt][0] += e00 + e10;
                scol[nt][1] += e01 + e11;
                size_t o0 = ((size_t)(b * 8 + h) * NSEQ + n) * 32 + e;
                *(__half2*)(g_eh + o0)       = __halves2half2(__float2half(e00), __float2half(e01));
                *(__half2*)(g_eh + o0 + 256) = __halves2half2(__float2half(e10), __float2half(e11));
            } else {                            // v
                int cv = c - 512;
                *(__half2*)(g_vh + (size_t)r * 256 + cv) =
                    __halves2half2(__float2half(p0.x), __float2half(p0.y));
                *(__half2*)(g_vh + (size_t)(r + 8) * 256 + cv) =
                    __halves2half2(__float2half(p1.x), __float2half(p1.y));
            }
        }
    }

    if (col0 == 256 || col0 == 384) {
        __syncthreads();
        float* sS = (float*)sm;  // [128 cols][16 groups]
        int grp = mw * 8 + (lane >> 2);
        #pragma unroll
        for (int nt = 0; nt < 4; nt++)
            #pragma unroll
            for (int p = 0; p < 2; p++) {
                int ckL = nw * 32 + nt * 8 + ((lane & 3) << 1) + p;
                sS[ckL * 16 + grp] = scol[nt][p];
            }
        __syncthreads();
        if (tid < 128) {
            float s = 0.f;
            #pragma unroll
            for (int g = 0; g < 16; g++) s += sS[tid * 16 + g];
            g_Sp2[(size_t)blockIdx.y * 256 + (col0 - 256) + tid] = s;
        }
    }
}

// ============================================================================
// K2: tensor-core stats, fp16 inputs / f32 accum (unchanged).
// ============================================================================
__global__ __launch_bounds__(256) void k_stats() {
    extern __shared__ __half sms[];
    int bh = blockIdx.x, seg = blockIdx.y;
    int tid = threadIdx.x, warp = tid >> 5, lane = tid & 31;

    __half* wbase = sms + warp * 2560;
    const size_t rowbase = ((size_t)bh * NSEQ + seg * SSEG + warp * 128) * 32;
    const __half* Q = g_qh + rowbase;
    const __half* E = g_eh + rowbase;

    const int lr = lane & 15;
    const int lc = (lane >> 4) * 16;

    auto prefetch = [&](int st, int s) {
        __half* sb = wbase + st * 1280;
        size_t src = (size_t)(s * 16 + lr) * 32 + lc;
        cp16(sb +   0 + lr * 40 + lc, Q + src);
        cp16(sb +   8 + lr * 40 + lc, Q + src + 8);
        cp16(sb + 640 + lr * 40 + lc, E + src);
        cp16(sb + 648 + lr * 40 + lc, E + src + 8);
        cp_commit();
    };

    float acc[2][4][4];
    #pragma unroll
    for (int dt = 0; dt < 2; dt++)
        #pragma unroll
        for (int nt = 0; nt < 4; nt++)
            #pragma unroll
            for (int i = 0; i < 4; i++) acc[dt][nt][i] = 0.f;

    const int ar = (lane & 7) | ((lane & 16) >> 1);
    const int ac = lane & 8;
    const int br = lane & 15;
    const int bc = (lane >> 4) << 3;

    prefetch(0, 0);
    for (int s = 0; s < 8; s++) {
        if (s < 7) { prefetch((s + 1) & 1, s + 1); cp_wait<1>(); }
        else cp_wait<0>();
        __syncwarp();
        __half* sb = wbase + (s & 1) * 1280;
        uint32_t Af[2][4], Bf[2][4];
        #pragma unroll
        for (int dt = 0; dt < 2; dt++)
            ldsm4t(Af[dt], sb + 640 + ar * 40 + dt * 16 + ac);
        #pragma unroll
        for (int et = 0; et < 2; et++)
            ldsm4t(Bf[et], sb + br * 40 + et * 16 + bc);
        #pragma unroll
        for (int dt = 0; dt < 2; dt++)
            #pragma unroll
            for (int nt = 0; nt < 4; nt++)
                mma16816h(acc[dt][nt], Af[dt], &Bf[nt >> 1][(nt & 1) * 2]);
        __syncwarp();
    }

    float* red = (float*)(sms + 8 * 2560);
    int gr = lane >> 2, tc = lane & 3;
    #pragma unroll
    for (int dt = 0; dt < 2; dt++)
        #pragma unroll
        for (int nt = 0; nt < 4; nt++) {
            int d0 = dt * 16 + gr, e0 = nt * 8 + tc * 2;
            red[warp * 1024 + d0 * 32 + e0]           = acc[dt][nt][0];
            red[warp * 1024 + d0 * 32 + e0 + 1]       = acc[dt][nt][1];
            red[warp * 1024 + (d0 + 8) * 32 + e0]     = acc[dt][nt][2];
            red[warp * 1024 + (d0 + 8) * 32 + e0 + 1] = acc[dt][nt][3];
        }
    __syncthreads();
    float* ap = g_Apart + ((size_t)bh * NSEG + seg) * 1024;
    #pragma unroll
    for (int c = 0; c < 4; c++) {
        int idx = tid * 4 + c;
        float s = 0.f;
        #pragma unroll
        for (int w = 0; w < 8; w++) s += red[w * 1024 + idx];
        ap[idx] = s;
    }
}

// ============================================================================
// K3a: combine -> g_A.  grid (64 bh, 4 quarters): block reduces 256 entries.
// sinv computed redundantly per block (parallel over 256 threads).
// ============================================================================
__global__ __launch_bounds__(256) void k_combine() {
    int bh = blockIdx.x, qtr = blockIdx.y, tid = threadIdx.x;
    int b = bh >> 3, h = bh & 7;
    __shared__ float partS[8][32];
    __shared__ float sinv[32];
    {
        int j = tid & 31, part = tid >> 5;
        float s = 0.f;
        #pragma unroll
        for (int r = 0; r < 8; r++)
            s += g_Sp2[(size_t)(b * 64 + part * 8 + r) * 256 + h * 32 + j];
        partS[part][j] = s;
    }
    __syncthreads();
    if (tid < 32) {
        float t = 0.f;
        #pragma unroll
        for (int w = 0; w < 8; w++) t += partS[w][tid];
        sinv[tid] = SCALE_ / t;
    }
    __syncthreads();
    int idx = qtr * 256 + tid;
    float a = 0.f;
    #pragma unroll
    for (int seg = 0; seg < NSEG; seg++)
        a += g_Apart[((size_t)bh * NSEG + seg) * 1024 + idx];
    g_A[bh * 1024 + idx] = a * sinv[idx >> 5];
}

// ============================================================================
// K3b: W2[bh][l*32+d][c] = W2SCALE * sum_e A[d][e]*Wout[l*32+e][c]  grid(64,8)
// ============================================================================
__global__ __launch_bounds__(256) void k_w2(const float* __restrict__ Wout) {
    __shared__ float A_s[1024];
    __shared__ float Wsh[32 * 256];
    int bh = blockIdx.x, l = blockIdx.y, tid = threadIdx.x;
    for (int i = tid; i < 1024; i += 256) A_s[i] = g_A[bh * 1024 + i];
    {
        const float4* wsrc = (const float4*)(Wout + l * 32 * 256);
        float4* wdst = (float4*)Wsh;
        for (int i = tid; i < 2048; i += 256) wdst[i] = wsrc[i];
    }
    __syncthreads();
    int c = tid;
    for (int d = 0; d < 32; d++) {
        float s = 0.f;
        #pragma unroll
        for (int e = 0; e < 32; e++) s += A_s[d * 32 + e] * Wsh[e * 256 + c];
        g_w2h[(size_t)bh * 65536 + (size_t)(l * 32 + d) * 256 + c] = __float2half(s * W2SCALE);
    }
}

// ============================================================================
// K4: per (b,h): Y = Vcat @ W2 * (1/W2SCALE) + bias, LayerNorm, write out.
// BM=128, BN=256, BK=32, 512 thr, 4 stages, single-sync mainloop.
// ============================================================================
#define K4_STG 13568
__global__ __launch_bounds__(512, 1) void k4_out(const float* __restrict__ bout,
                                                 const float* __restrict__ gamma,
                                                 const float* __restrict__ beta,
                                                 float* __restrict__ out) {
    extern __shared__ __half sm[];
    const int tid = threadIdx.x, lane = tid & 31, warp = tid >> 5;
    const int mw = warp >> 3, nw = warp & 7;
    const int bh = blockIdx.y, b = bh >> 3, h = bh & 7;
    const int t0 = blockIdx.x * 128;

    __half *sA[4], *sB[4];
    #pragma unroll
    for (int s = 0; s < 4; s++) {
        sA[s] = sm + s * K4_STG;
        sB[s] = sm + s * K4_STG + 5120;
    }

    auto load_stage = [&](int s, int kt) {
        {
            int ar = tid >> 2; int ac = (tid & 3) * 8;
            const size_t go = ((size_t)(b * 8192) + (size_t)(t0 + ar) * 8 + kt) * 256 + h * 32 + ac;
            cp16(sA[s] + ar * 40 + ac, g_vh + go);
        }
        #pragma unroll
        for (int i = 0; i < 2; i++) {
            int id = tid * 2 + i; int br = id >> 5; int bc = (id & 31) * 8;
            const size_t go = (size_t)bh * 65536 + (size_t)(kt * 32 + br) * 256 + bc;
            cp16(sB[s] + br * 264 + bc, g_w2h + go);
        }
        cp_commit();
    };

    float acc[4][4][4];
    #pragma unroll
    for (int mt = 0; mt < 4; mt++)
        #pragma unroll
        for (int nt = 0; nt < 4; nt++)
            #pragma unroll
            for (int i = 0; i < 4; i++) acc[mt][nt][i] = 0.f;

    load_stage(0, 0);
    load_stage(1, 1);
    load_stage(2, 2);
    for (int kt = 0; kt < 8; kt++) {
        int cur = kt & 3;
        if (kt < 6)       cp_wait<2>();
        else if (kt == 6) cp_wait<1>();
        else              cp_wait<0>();
        __syncthreads();
        if (kt < 5) load_stage((kt + 3) & 3, kt + 3);
        #pragma unroll
        for (int sub = 0; sub < 2; sub++) {
            uint32_t af[4][4], bf[2][4];
            #pragma unroll
            for (int mt = 0; mt < 4; mt++) {
                int r = mw * 64 + mt * 16 + (lane & 15);
                int c = sub * 16 + ((lane >> 4) << 3);
                ldsm4(af[mt], sA[cur] + r * 40 + c);
            }
            #pragma unroll
            for (int bt = 0; bt < 2; bt++) {
                int r = sub * 16 + (lane & 15);
                int c = nw * 32 + bt * 16 + ((lane >> 4) << 3);
                ldsm4t(bf[bt], sB[cur] + r * 264 + c);
            }
            #pragma unroll
            for (int mt = 0; mt < 4; mt++)
                #pragma unroll
                for (int nt = 0; nt < 4; nt++)
                    mma16816h(acc[mt][nt], af[mt], &bf[nt >> 1][(nt & 1) * 2]);
        }
    }
    __syncthreads();

    // ---------------- epilogue: unscale + bias + LayerNorm --------------------
    float* red   = (float*)sm;
    float* sred  = red;            // [128][8]
    float* s2red = red + 1024;     // [128][8]
    float* mus   = red + 2048;     // [128]
    float* rst   = red + 2176;     // [128]

    float bo[4][2];
    #pragma unroll
    for (int nt = 0; nt < 4; nt++) {
        int c = nw * 32 + nt * 8 + ((lane & 3) << 1);
        float2 bv = *(const float2*)(bout + c);
        bo[nt][0] = bv.x; bo[nt][1] = bv.y;
    }

    #pragma unroll
    for (int mt = 0; mt < 4; mt++)
        #pragma unroll
        for (int half = 0; half < 2; half++) {
            float s = 0.f, s2 = 0.f;
            #pragma unroll
            for (int nt = 0; nt < 4; nt++) {
                float v0 = acc[mt][nt][half * 2 + 0] * W2INV + bo[nt][0];
                float v1 = acc[mt][nt][half * 2 + 1] * W2INV + bo[nt][1];
                s += v0 + v1; s2 += v0 * v0 + v1 * v1;
            }
            s  += __shfl_xor_sync(0xffffffffu, s, 1);
            s  += __shfl_xor_sync(0xffffffffu, s, 2);
            s2 += __shfl_xor_sync(0xffffffffu, s2, 1);
            s2 += __shfl_xor_sync(0xffffffffu, s2, 2);
            if ((lane & 3) == 0) {
                int rl = mw * 64 + mt * 16 + (lane >> 2) + half * 8;
                sred[rl * 8 + nw] = s;
                s2red[rl * 8 + nw] = s2;
            }
        }
    __syncthreads();
    if (tid < 128) {
        float s = 0.f, s2 = 0.f;
        #pragma unroll
        for (int w = 0; w < 8; w++) { s += sred[tid * 8 + w]; s2 += s2red[tid * 8 + w]; }
        float mu = s * (1.f / 256.f);
        float var = s2 * (1.f / 256.f) - mu * mu;
        mus[tid] = mu;
        rst[tid] = rsqrtf(var + LN_EPS);
    }
    __syncthreads();

    #pragma unroll
    for (int mt = 0; mt < 4; mt++)
        #pragma unroll
        for (int half = 0; half < 2; half++) {
            int rl = mw * 64 + mt * 16 + (lane >> 2) + half * 8;
            float mu = mus[rl], rs = rst[rl];
            size_t orow = ((size_t)b * 8192 + (size_t)h * 1024 + t0 + rl) * 256;
            #pragma unroll
            for (int nt = 0; nt < 4; nt++) {
                int c = nw * 32 + nt * 8 + ((lane & 3) << 1);
                float2 g = *(const float2*)(gamma + c);
                float2 be = *(const float2*)(beta + c);
                float v0 = acc[mt][nt][half * 2 + 0] * W2INV + bo[nt][0];
                float v1 = acc[mt][nt][half * 2 + 1] * W2INV + bo[nt][1];
                float2 o = make_float2((v0 - mu) * rs * g.x + be.x,
                                       (v1 - mu) * rs * g.y + be.y);
                *(float2*)(out + orow + c) = o;
            }
        }
}

// ============================================================================
extern "C" void kernel_launch(void* const* d_in, const int* in_sizes, int n_in,
                              void* d_out, int out_size) {
    const float* x     = (const float*)d_in[0];
    const float* Wqkv  = (const float*)d_in[1];
    const float* Wout  = (const float*)d_in[2];
    const float* bout  = (const float*)d_in[3];
    const float* gamma = (const float*)d_in[4];
    const float* beta  = (const float*)d_in[5];
    float* out = (float*)d_out;

    const int statsSmem = 8 * 2560 * 2 + 8 * 1024 * 4;
    cudaFuncSetAttribute(k1_gemm, cudaFuncAttributeMaxDynamicSharedMemorySize, 4 * K1_STG * 2);
    cudaFuncSetAttribute(k_stats, cudaFuncAttributeMaxDynamicSharedMemorySize, statsSmem);
    cudaFuncSetAttribute(k4_out,  cudaFuncAttributeMaxDynamicSharedMemorySize, 4 * K4_STG * 2);

    k_cvt<<<16576, 256>>>(x, Wqkv);
    k1_gemm<<<dim3(6, 512), 256, 4 * K1_STG * 2>>>();
    k_stats<<<dim3(64, NSEG), 256, statsSmem>>>();
    k_combine<<<dim3(64, 4), 256>>>();
    k_w2<<<dim3(64, 8), 256>>>(Wout);
    k4_out<<<dim3(8, 64), 512, 4 * K4_STG * 2>>>(bout, gamma, beta, out);
}